// round 12
// baseline (speedup 1.0000x reference)
#include <cuda_runtime.h>
#include <cuda_fp16.h>

#define BB 16
#define CC 192
#define HH 64
#define WW 64
#define LL (HH*WW)      // 4096
#define RR 12           // dt_rank
#define NK 14           // dt_rank + 2*d_state

// Scratch (no cudaMalloc allowed)
__device__ float  g_xs[(size_t)BB*CC*LL];       // 50.3 MB  conv+SiLU output
__device__ __half g_delta_h[(size_t)BB*CC*LL];  // 25.2 MB  softplus(dt-proj), fp16
__device__ float  g_bc[(size_t)BB*2*LL];        // 0.5 MB   Bs, Cs rows

// ---------------------------------------------------------------------------
// K1: depthwise 5x5 conv (SAME) + bias + SiLU.
// 4 outputs per thread along x: per window row, 2 LDS.128 (8 floats) feed
// 20 FMAs -> 2.5 LDS/output, zero shift-MOVs. Tile rows padded to 72 floats
// so every LDS.128 is 16B-aligned.
// ---------------------------------------------------------------------------
#define TP 72   // padded tile row stride (floats)

__global__ __launch_bounds__(256) void conv_silu_kernel(
    const float* __restrict__ x,
    const float* __restrict__ cw,
    const float* __restrict__ cb)
{
    int bc = blockIdx.x;            // b*CC + c
    int c  = bc % CC;
    __shared__ float s[68 * TP];
    const float* img = x + (size_t)bc * LL;
    int tid = threadIdx.x;

    // load 68x68 padded tile (zeros outside), row stride TP
    for (int idx = tid; idx < 68 * 68; idx += 256) {
        int yy = idx / 68, xx = idx % 68;
        int iy = yy - 2, ix = xx - 2;
        float v = 0.f;
        if (iy >= 0 && iy < HH && ix >= 0 && ix < WW) v = img[iy * WW + ix];
        s[yy * TP + xx] = v;
    }

    float w[25];
#pragma unroll
    for (int i = 0; i < 25; i++) w[i] = __ldg(&cw[c * 25 + i]);
    float bias = __ldg(&cb[c]);
    __syncthreads();

    int x0 = (tid & 15) * 4;        // output cols x0..x0+3
    int r  = tid >> 4;              // 0..15; rows r, r+16, r+32, r+48
    float* dst = g_xs + (size_t)bc * LL;

#pragma unroll
    for (int yi = 0; yi < 4; yi++) {
        int y = r + yi * 16;
        float a0 = bias, a1 = bias, a2 = bias, a3 = bias;
#pragma unroll
        for (int dy = 0; dy < 5; dy++) {
            const float4* pr = (const float4*)&s[(y + dy) * TP + x0];
            float4 lo = pr[0], hi = pr[1];
            float v0 = lo.x, v1 = lo.y, v2 = lo.z, v3 = lo.w;
            float v4 = hi.x, v5 = hi.y, v6 = hi.z, v7 = hi.w;
            float w0 = w[dy*5+0], w1 = w[dy*5+1], w2 = w[dy*5+2];
            float w3 = w[dy*5+3], w4 = w[dy*5+4];
            a0 = fmaf(v0, w0, a0); a1 = fmaf(v1, w0, a1);
            a2 = fmaf(v2, w0, a2); a3 = fmaf(v3, w0, a3);
            a0 = fmaf(v1, w1, a0); a1 = fmaf(v2, w1, a1);
            a2 = fmaf(v3, w1, a2); a3 = fmaf(v4, w1, a3);
            a0 = fmaf(v2, w2, a0); a1 = fmaf(v3, w2, a1);
            a2 = fmaf(v4, w2, a2); a3 = fmaf(v5, w2, a3);
            a0 = fmaf(v3, w3, a0); a1 = fmaf(v4, w3, a1);
            a2 = fmaf(v5, w3, a2); a3 = fmaf(v6, w3, a3);
            a0 = fmaf(v4, w4, a0); a1 = fmaf(v5, w4, a1);
            a2 = fmaf(v6, w4, a2); a3 = fmaf(v7, w4, a3);
        }
        // SiLU
        float e0 = exp2f(-a0 * 1.44269504f);
        float e1 = exp2f(-a1 * 1.44269504f);
        float e2 = exp2f(-a2 * 1.44269504f);
        float e3 = exp2f(-a3 * 1.44269504f);
        float4 o4 = make_float4(__fdividef(a0, 1.f + e0),
                                __fdividef(a1, 1.f + e1),
                                __fdividef(a2, 1.f + e2),
                                __fdividef(a3, 1.f + e3));
        *(float4*)(dst + y * WW + x0) = o4;
    }
}

// ---------------------------------------------------------------------------
// K2: fused x_proj + dt-projection + softplus (R9 form, unchanged — at FMA floor).
// ---------------------------------------------------------------------------
__global__ __launch_bounds__(256) void xproj_delta_kernel(
    const float* __restrict__ xw,     // (14, C)
    const float* __restrict__ dtw,    // (C, 12)
    const float* __restrict__ dtb)    // (C,)
{
    __shared__ float sw [96 * 32];    // [ci][half][16]
    __shared__ float sdt[96 * 32];    // [ci][half][16]
    __shared__ float sdb[CC];
    int t = threadIdx.x;
    for (int i = t; i < 96 * 32; i += 256) { sw[i] = 0.f; sdt[i] = 0.f; }
    __syncthreads();
    for (int i = t; i < NK * CC; i += 256) {
        int k = i / CC, c = i % CC;
        int ci = c % 96, hf = c / 96;
        sw[ci * 32 + hf * 16 + k] = xw[i];
    }
    for (int i = t; i < CC * RR; i += 256) {
        int c = i / RR, r = i % RR;
        int ci = c % 96, hf = c / 96;
        sdt[ci * 32 + hf * 16 + r] = dtw[i];
    }
    for (int i = t; i < CC; i += 256) sdb[i] = dtb[i];
    __syncthreads();

    int half = t & 1;
    int li   = t >> 1;
    int b = blockIdx.y;
    int l = blockIdx.x * 128 + li;
    const float* xs = g_xs + (size_t)b * CC * LL + l;
    int cbase = half * 96;

    float acc[NK];
#pragma unroll
    for (int k = 0; k < NK; k++) acc[k] = 0.f;

#pragma unroll 8
    for (int ci = 0; ci < 96; ci++) {
        int c = cbase + ci;
        float v = xs[(size_t)c * LL];
        const float4* wp4 = (const float4*)&sw[ci * 32 + half * 16];
        float4 w0 = wp4[0], w1 = wp4[1], w2 = wp4[2], w3 = wp4[3];
        acc[0]  = fmaf(w0.x, v, acc[0]);
        acc[1]  = fmaf(w0.y, v, acc[1]);
        acc[2]  = fmaf(w0.z, v, acc[2]);
        acc[3]  = fmaf(w0.w, v, acc[3]);
        acc[4]  = fmaf(w1.x, v, acc[4]);
        acc[5]  = fmaf(w1.y, v, acc[5]);
        acc[6]  = fmaf(w1.z, v, acc[6]);
        acc[7]  = fmaf(w1.w, v, acc[7]);
        acc[8]  = fmaf(w2.x, v, acc[8]);
        acc[9]  = fmaf(w2.y, v, acc[9]);
        acc[10] = fmaf(w2.z, v, acc[10]);
        acc[11] = fmaf(w2.w, v, acc[11]);
        acc[12] = fmaf(w3.x, v, acc[12]);
        acc[13] = fmaf(w3.y, v, acc[13]);
    }

#pragma unroll
    for (int k = 0; k < NK; k++)
        acc[k] += __shfl_xor_sync(0xffffffffu, acc[k], 1);

    if (half == 0) {
        float* bcp = g_bc + (size_t)b * 2 * LL + l;
        bcp[0]  = acc[12];
        bcp[LL] = acc[13];
    }

    __half* dl = g_delta_h + (size_t)b * CC * LL + l;
#pragma unroll 4
    for (int ci = 0; ci < 96; ci++) {
        int c = cbase + ci;
        const float4* dwp = (const float4*)&sdt[ci * 32 + half * 16];
        float4 d0 = dwp[0], d1 = dwp[1], d2 = dwp[2];
        float dxv = sdb[c];
        dxv = fmaf(d0.x, acc[0], dxv);
        dxv = fmaf(d0.y, acc[1], dxv);
        dxv = fmaf(d0.z, acc[2], dxv);
        dxv = fmaf(d0.w, acc[3], dxv);
        dxv = fmaf(d1.x, acc[4], dxv);
        dxv = fmaf(d1.y, acc[5], dxv);
        dxv = fmaf(d1.z, acc[6], dxv);
        dxv = fmaf(d1.w, acc[7], dxv);
        dxv = fmaf(d2.x, acc[8], dxv);
        dxv = fmaf(d2.y, acc[9], dxv);
        dxv = fmaf(d2.z, acc[10], dxv);
        dxv = fmaf(d2.w, acc[11], dxv);

        float tx  = __log2f(1.f + exp2f(dxv * 1.44269504f)) * 0.69314718f;
        float spx = (dxv > 20.f) ? dxv : tx;
        dl[(size_t)c * LL] = __float2half_rn(spx);
    }
}

// ---------------------------------------------------------------------------
// K3: selective scan (d_state=1) + output. Warp-striped; a and delta*B*x are
// cached in registers during the compose pass -> replay has NO exp2/mul
// (halves MUFU work), zero net register delta vs R9.
// ---------------------------------------------------------------------------
#define TPB3 256
#define NCH  4

__global__ __launch_bounds__(TPB3) void scan_kernel(
    const float* __restrict__ A_logs,
    const float* __restrict__ Ds,
    float* __restrict__ out)
{
    int bc = blockIdx.x;
    int b = bc / CC, c = bc % CC;
    int t = threadIdx.x;
    int lane = t & 31, wid = t >> 5;
    int wbase = wid * 512;

    const float*  xs_row = g_xs      + (size_t)bc * LL;
    const __half* dl_row = g_delta_h + (size_t)bc * LL;
    const float*  Bs_row = g_bc + (size_t)b * 2 * LL;
    const float*  Cs_row = Bs_row + LL;

    float Dv  = __ldg(&Ds[c]);
    float Al2 = -1.44269504f * __expf(__ldg(&A_logs[c]));

    float av[NCH][4], btv[NCH][4], xv[NCH][4];
    float Ain[NCH], Bin[NCH];
    float carryA = 1.f, carryB = 0.f;

#pragma unroll
    for (int j = 0; j < NCH; j++) {
        int l = wbase + j * 128 + lane * 4;
        uint2 raw = *(const uint2*)(dl_row + l);
        float2 f01 = __half22float2(*(__half2*)&raw.x);
        float2 f23 = __half22float2(*(__half2*)&raw.y);
        float dvk[4] = {f01.x, f01.y, f23.x, f23.y};
        float4 x4 = *(const float4*)(xs_row + l);
        float4 b4 = *(const float4*)(Bs_row + l);
        xv[j][0]=x4.x; xv[j][1]=x4.y; xv[j][2]=x4.z; xv[j][3]=x4.w;
        float bsv[4] = {b4.x, b4.y, b4.z, b4.w};

        float Ac = 1.f, Bc = 0.f;
#pragma unroll
        for (int k = 0; k < 4; k++) {
            float a  = exp2f(Al2 * dvk[k]);
            float bt = dvk[k] * bsv[k] * xv[j][k];
            av[j][k]  = a;
            btv[j][k] = bt;
            Ac = a * Ac;
            Bc = fmaf(a, Bc, bt);
        }

        float Asc = Ac, Bsc = Bc;
#pragma unroll
        for (int off = 1; off < 32; off <<= 1) {
            float aU = __shfl_up_sync(0xffffffffu, Asc, off);
            float bU = __shfl_up_sync(0xffffffffu, Bsc, off);
            if (lane >= off) { Bsc = fmaf(Asc, bU, Bsc); Asc *= aU; }
        }
        float aEx = __shfl_up_sync(0xffffffffu, Asc, 1);
        float bEx = __shfl_up_sync(0xffffffffu, Bsc, 1);
        if (lane == 0) { aEx = 1.f; bEx = 0.f; }
        Ain[j] = aEx * carryA;
        Bin[j] = fmaf(aEx, carryB, bEx);
        float aT = __shfl_sync(0xffffffffu, Asc, 31);
        float bT = __shfl_sync(0xffffffffu, Bsc, 31);
        carryB = fmaf(aT, carryB, bT);
        carryA = aT * carryA;
    }

    __shared__ float swA[TPB3/32], swB[TPB3/32];
    if (lane == 0) { swA[wid] = carryA; swB[wid] = carryB; }
    __syncthreads();
    float Hws = 0.f;
    for (int wp = 0; wp < wid; wp++) Hws = fmaf(swA[wp], Hws, swB[wp]);

    float* out_row = out + (size_t)bc * LL;
#pragma unroll
    for (int j = 0; j < NCH; j++) {
        int l = wbase + j * 128 + lane * 4;
        float4 c4 = *(const float4*)(Cs_row + l);
        float csv[4] = {c4.x, c4.y, c4.z, c4.w};
        float h = fmaf(Ain[j], Hws, Bin[j]);
        float yo[4];
#pragma unroll
        for (int k = 0; k < 4; k++) {
            h = fmaf(av[j][k], h, btv[j][k]);
            yo[k] = fmaf(h, csv[k], xv[j][k] * Dv);
        }
        *(float4*)(out_row + l) = make_float4(yo[0], yo[1], yo[2], yo[3]);
    }
}

// ---------------------------------------------------------------------------
extern "C" void kernel_launch(void* const* d_in, const int* in_sizes, int n_in,
                              void* d_out, int out_size)
{
    const float* x        = (const float*)d_in[0];
    const float* conv_w   = (const float*)d_in[1];
    const float* conv_b   = (const float*)d_in[2];
    const float* x_proj_w = (const float*)d_in[3];
    const float* dt_w     = (const float*)d_in[4];
    const float* dt_b     = (const float*)d_in[5];
    const float* A_logs   = (const float*)d_in[6];
    const float* Ds       = (const float*)d_in[7];
    float* out = (float*)d_out;

    conv_silu_kernel<<<BB * CC, 256>>>(x, conv_w, conv_b);
    xproj_delta_kernel<<<dim3(LL / 128, BB), 256>>>(x_proj_w, dt_w, dt_b);
    scan_kernel<<<BB * CC, TPB3>>>(A_logs, Ds, out);
}

// round 13
// speedup vs baseline: 1.0515x; 1.0515x over previous
#include <cuda_runtime.h>
#include <cuda_fp16.h>

#define BB 16
#define CC 192
#define HH 64
#define WW 64
#define LL (HH*WW)      // 4096
#define RR 12           // dt_rank
#define NK 14           // dt_rank + 2*d_state

// Scratch (no cudaMalloc allowed)
__device__ __half g_xs_h[(size_t)BB*CC*LL];     // 25.2 MB  conv+SiLU output, fp16
__device__ __half g_delta_h[(size_t)BB*CC*LL];  // 25.2 MB  softplus(dt-proj), fp16
__device__ float  g_bc[(size_t)BB*2*LL];        // 0.5 MB   Bs, Cs rows

// ---------------------------------------------------------------------------
// K1: depthwise 5x5 conv (SAME) + bias + SiLU.  (R6 rolling-window form —
// the proven 44.6us operating point; only the store dtype changed to fp16.)
// ---------------------------------------------------------------------------
__global__ __launch_bounds__(256) void conv_silu_kernel(
    const float* __restrict__ x,
    const float* __restrict__ cw,
    const float* __restrict__ cb)
{
    int bc = blockIdx.x;            // b*CC + c
    int c  = bc % CC;
    __shared__ float s[68 * 68];
    const float* img = x + (size_t)bc * LL;
    int tid = threadIdx.x;

    for (int idx = tid; idx < 68 * 68; idx += 256) {
        int yy = idx / 68, xx = idx % 68;
        int iy = yy - 2, ix = xx - 2;
        float v = 0.f;
        if (iy >= 0 && iy < HH && ix >= 0 && ix < WW) v = img[iy * WW + ix];
        s[idx] = v;
    }

    float w[25];
#pragma unroll
    for (int i = 0; i < 25; i++) w[i] = __ldg(&cw[c * 25 + i]);
    float bias = __ldg(&cb[c]);
    __syncthreads();

    int xcol = tid & 63;
    int y0   = (tid >> 6) * 16;
    __half* dst = g_xs_h + (size_t)bc * LL;

    float win[5][5];
#pragma unroll
    for (int dy = 0; dy < 4; dy++)
#pragma unroll
        for (int dx = 0; dx < 5; dx++)
            win[dy][dx] = s[(y0 + dy) * 68 + xcol + dx];

#pragma unroll
    for (int i = 0; i < 16; i++) {
        int y = y0 + i;
#pragma unroll
        for (int dx = 0; dx < 5; dx++)
            win[4][dx] = s[(y + 4) * 68 + xcol + dx];

        float acc0 = bias, acc1 = 0.f;
#pragma unroll
        for (int dy = 0; dy < 5; dy++) {
#pragma unroll
            for (int dx = 0; dx < 5; dx++) {
                if (((dy * 5 + dx) & 1) == 0) acc0 = fmaf(win[dy][dx], w[dy*5+dx], acc0);
                else                          acc1 = fmaf(win[dy][dx], w[dy*5+dx], acc1);
            }
        }
        float acc = acc0 + acc1;

        float e = exp2f(-acc * 1.44269504f);
        dst[y * WW + xcol] = __float2half_rn(__fdividef(acc, 1.f + e));

#pragma unroll
        for (int dy = 0; dy < 4; dy++)
#pragma unroll
            for (int dx = 0; dx < 5; dx++)
                win[dy][dx] = win[dy + 1][dx];
    }
}

// ---------------------------------------------------------------------------
// K2: fused x_proj + dt-projection + softplus (R9/R12 form; xs now fp16).
// ---------------------------------------------------------------------------
__global__ __launch_bounds__(256) void xproj_delta_kernel(
    const float* __restrict__ xw,     // (14, C)
    const float* __restrict__ dtw,    // (C, 12)
    const float* __restrict__ dtb)    // (C,)
{
    __shared__ float sw [96 * 32];    // [ci][half][16]
    __shared__ float sdt[96 * 32];    // [ci][half][16]
    __shared__ float sdb[CC];
    int t = threadIdx.x;
    for (int i = t; i < 96 * 32; i += 256) { sw[i] = 0.f; sdt[i] = 0.f; }
    __syncthreads();
    for (int i = t; i < NK * CC; i += 256) {
        int k = i / CC, c = i % CC;
        int ci = c % 96, hf = c / 96;
        sw[ci * 32 + hf * 16 + k] = xw[i];
    }
    for (int i = t; i < CC * RR; i += 256) {
        int c = i / RR, r = i % RR;
        int ci = c % 96, hf = c / 96;
        sdt[ci * 32 + hf * 16 + r] = dtw[i];
    }
    for (int i = t; i < CC; i += 256) sdb[i] = dtb[i];
    __syncthreads();

    int half = t & 1;
    int li   = t >> 1;
    int b = blockIdx.y;
    int l = blockIdx.x * 128 + li;
    const __half* xs = g_xs_h + (size_t)b * CC * LL + l;
    int cbase = half * 96;

    float acc[NK];
#pragma unroll
    for (int k = 0; k < NK; k++) acc[k] = 0.f;

#pragma unroll 8
    for (int ci = 0; ci < 96; ci++) {
        int c = cbase + ci;
        float v = __half2float(xs[(size_t)c * LL]);
        const float4* wp4 = (const float4*)&sw[ci * 32 + half * 16];
        float4 w0 = wp4[0], w1 = wp4[1], w2 = wp4[2], w3 = wp4[3];
        acc[0]  = fmaf(w0.x, v, acc[0]);
        acc[1]  = fmaf(w0.y, v, acc[1]);
        acc[2]  = fmaf(w0.z, v, acc[2]);
        acc[3]  = fmaf(w0.w, v, acc[3]);
        acc[4]  = fmaf(w1.x, v, acc[4]);
        acc[5]  = fmaf(w1.y, v, acc[5]);
        acc[6]  = fmaf(w1.z, v, acc[6]);
        acc[7]  = fmaf(w1.w, v, acc[7]);
        acc[8]  = fmaf(w2.x, v, acc[8]);
        acc[9]  = fmaf(w2.y, v, acc[9]);
        acc[10] = fmaf(w2.z, v, acc[10]);
        acc[11] = fmaf(w2.w, v, acc[11]);
        acc[12] = fmaf(w3.x, v, acc[12]);
        acc[13] = fmaf(w3.y, v, acc[13]);
    }

#pragma unroll
    for (int k = 0; k < NK; k++)
        acc[k] += __shfl_xor_sync(0xffffffffu, acc[k], 1);

    if (half == 0) {
        float* bcp = g_bc + (size_t)b * 2 * LL + l;
        bcp[0]  = acc[12];
        bcp[LL] = acc[13];
    }

    __half* dl = g_delta_h + (size_t)b * CC * LL + l;
#pragma unroll 4
    for (int ci = 0; ci < 96; ci++) {
        int c = cbase + ci;
        const float4* dwp = (const float4*)&sdt[ci * 32 + half * 16];
        float4 d0 = dwp[0], d1 = dwp[1], d2 = dwp[2];
        float dxv = sdb[c];
        dxv = fmaf(d0.x, acc[0], dxv);
        dxv = fmaf(d0.y, acc[1], dxv);
        dxv = fmaf(d0.z, acc[2], dxv);
        dxv = fmaf(d0.w, acc[3], dxv);
        dxv = fmaf(d1.x, acc[4], dxv);
        dxv = fmaf(d1.y, acc[5], dxv);
        dxv = fmaf(d1.z, acc[6], dxv);
        dxv = fmaf(d1.w, acc[7], dxv);
        dxv = fmaf(d2.x, acc[8], dxv);
        dxv = fmaf(d2.y, acc[9], dxv);
        dxv = fmaf(d2.z, acc[10], dxv);
        dxv = fmaf(d2.w, acc[11], dxv);

        float tx  = __log2f(1.f + exp2f(dxv * 1.44269504f)) * 0.69314718f;
        float spx = (dxv > 20.f) ? dxv : tx;
        dl[(size_t)c * LL] = __float2half_rn(spx);
    }
}

// ---------------------------------------------------------------------------
// K3: selective scan (d_state=1) + output (R12 caching form; xs now fp16).
// ---------------------------------------------------------------------------
#define TPB3 256
#define NCH  4

__global__ __launch_bounds__(TPB3) void scan_kernel(
    const float* __restrict__ A_logs,
    const float* __restrict__ Ds,
    float* __restrict__ out)
{
    int bc = blockIdx.x;
    int b = bc / CC, c = bc % CC;
    int t = threadIdx.x;
    int lane = t & 31, wid = t >> 5;
    int wbase = wid * 512;

    const __half* xs_row = g_xs_h    + (size_t)bc * LL;
    const __half* dl_row = g_delta_h + (size_t)bc * LL;
    const float*  Bs_row = g_bc + (size_t)b * 2 * LL;
    const float*  Cs_row = Bs_row + LL;

    float Dv  = __ldg(&Ds[c]);
    float Al2 = -1.44269504f * __expf(__ldg(&A_logs[c]));

    float av[NCH][4], btv[NCH][4], xv[NCH][4];
    float Ain[NCH], Bin[NCH];
    float carryA = 1.f, carryB = 0.f;

#pragma unroll
    for (int j = 0; j < NCH; j++) {
        int l = wbase + j * 128 + lane * 4;
        uint2 rawd = *(const uint2*)(dl_row + l);
        float2 d01 = __half22float2(*(__half2*)&rawd.x);
        float2 d23 = __half22float2(*(__half2*)&rawd.y);
        float dvk[4] = {d01.x, d01.y, d23.x, d23.y};
        uint2 rawx = *(const uint2*)(xs_row + l);
        float2 x01 = __half22float2(*(__half2*)&rawx.x);
        float2 x23 = __half22float2(*(__half2*)&rawx.y);
        xv[j][0]=x01.x; xv[j][1]=x01.y; xv[j][2]=x23.x; xv[j][3]=x23.y;
        float4 b4 = *(const float4*)(Bs_row + l);
        float bsv[4] = {b4.x, b4.y, b4.z, b4.w};

        float Ac = 1.f, Bc = 0.f;
#pragma unroll
        for (int k = 0; k < 4; k++) {
            float a  = exp2f(Al2 * dvk[k]);
            float bt = dvk[k] * bsv[k] * xv[j][k];
            av[j][k]  = a;
            btv[j][k] = bt;
            Ac = a * Ac;
            Bc = fmaf(a, Bc, bt);
        }

        float Asc = Ac, Bsc = Bc;
#pragma unroll
        for (int off = 1; off < 32; off <<= 1) {
            float aU = __shfl_up_sync(0xffffffffu, Asc, off);
            float bU = __shfl_up_sync(0xffffffffu, Bsc, off);
            if (lane >= off) { Bsc = fmaf(Asc, bU, Bsc); Asc *= aU; }
        }
        float aEx = __shfl_up_sync(0xffffffffu, Asc, 1);
        float bEx = __shfl_up_sync(0xffffffffu, Bsc, 1);
        if (lane == 0) { aEx = 1.f; bEx = 0.f; }
        Ain[j] = aEx * carryA;
        Bin[j] = fmaf(aEx, carryB, bEx);
        float aT = __shfl_sync(0xffffffffu, Asc, 31);
        float bT = __shfl_sync(0xffffffffu, Bsc, 31);
        carryB = fmaf(aT, carryB, bT);
        carryA = aT * carryA;
    }

    __shared__ float swA[TPB3/32], swB[TPB3/32];
    if (lane == 0) { swA[wid] = carryA; swB[wid] = carryB; }
    __syncthreads();
    float Hws = 0.f;
    for (int wp = 0; wp < wid; wp++) Hws = fmaf(swA[wp], Hws, swB[wp]);

    float* out_row = out + (size_t)bc * LL;
#pragma unroll
    for (int j = 0; j < NCH; j++) {
        int l = wbase + j * 128 + lane * 4;
        float4 c4 = *(const float4*)(Cs_row + l);
        float csv[4] = {c4.x, c4.y, c4.z, c4.w};
        float h = fmaf(Ain[j], Hws, Bin[j]);
        float yo[4];
#pragma unroll
        for (int k = 0; k < 4; k++) {
            h = fmaf(av[j][k], h, btv[j][k]);
            yo[k] = fmaf(h, csv[k], xv[j][k] * Dv);
        }
        *(float4*)(out_row + l) = make_float4(yo[0], yo[1], yo[2], yo[3]);
    }
}

// ---------------------------------------------------------------------------
extern "C" void kernel_launch(void* const* d_in, const int* in_sizes, int n_in,
                              void* d_out, int out_size)
{
    const float* x        = (const float*)d_in[0];
    const float* conv_w   = (const float*)d_in[1];
    const float* conv_b   = (const float*)d_in[2];
    const float* x_proj_w = (const float*)d_in[3];
    const float* dt_w     = (const float*)d_in[4];
    const float* dt_b     = (const float*)d_in[5];
    const float* A_logs   = (const float*)d_in[6];
    const float* Ds       = (const float*)d_in[7];
    float* out = (float*)d_out;

    conv_silu_kernel<<<BB * CC, 256>>>(x, conv_w, conv_b);
    xproj_delta_kernel<<<dim3(LL / 128, BB), 256>>>(x_proj_w, dt_w, dt_b);
    scan_kernel<<<BB * CC, TPB3>>>(A_logs, Ds, out);
}

// round 17
// speedup vs baseline: 1.2471x; 1.1861x over previous
#include <cuda_runtime.h>
#include <cuda_fp16.h>

#define BB 16
#define CC 192
#define HH 64
#define WW 64
#define LL (HH*WW)      // 4096
#define RR 12           // dt_rank
#define NK 14           // dt_rank + 2*d_state

// Scratch (no cudaMalloc allowed)
__device__ __half g_xs_h[(size_t)BB*CC*LL];     // 25.2 MB  conv+SiLU output, fp16
__device__ __half g_delta_h[(size_t)BB*CC*LL];  // 25.2 MB  softplus(dt-proj), fp16
__device__ float  g_bc[(size_t)BB*2*LL];        // 0.5 MB   Bs, Cs rows

// ---------------------------------------------------------------------------
// K1: depthwise 5x5 conv (SAME) + bias + SiLU.
// NEW loader: interior 64x64 via unpredicated LDG.128 (4/thread, no div/mod),
// halo (528 elems) zeroed in 3 predicated iterations. Main loop = proven
// R6 rolling-window form, fp16 store.
// ---------------------------------------------------------------------------
__global__ __launch_bounds__(256) void conv_silu_kernel(
    const float* __restrict__ x,
    const float* __restrict__ cw,
    const float* __restrict__ cb)
{
    int bc = blockIdx.x;            // b*CC + c
    int c  = bc % CC;
    __shared__ float s[68 * 68];
    const float* img = x + (size_t)bc * LL;
    int tid = threadIdx.x;

    // ---- halo zero: rows {0,1,66,67} full width + rows 2..65 cols {0,1,66,67}
#pragma unroll
    for (int it = 0; it < 3; it++) {
        int i = tid + it * 256;
        if (i < 528) {
            int row, col;
            if (i < 272) {
                int r4 = i / 68;
                row = (r4 < 2) ? r4 : (r4 + 64);   // 0,1,66,67
                col = i % 68;
            } else {
                int j = i - 272;
                row = 2 + (j >> 2);
                int c4 = j & 3;
                col = (c4 < 2) ? c4 : (c4 + 64);   // 0,1,66,67
            }
            s[row * 68 + col] = 0.f;
        }
    }

    // ---- interior: image row = tid>>2, col chunk = (tid&3)*16, 16 floats
    {
        int row = tid >> 2;
        int col = (tid & 3) * 16;
        const float4* src = (const float4*)(img + row * WW + col);
        float* drow = &s[(row + 2) * 68 + 2 + col];
#pragma unroll
        for (int q = 0; q < 4; q++) {
            float4 v = src[q];
            *(float2*)(drow + q * 4)     = make_float2(v.x, v.y);
            *(float2*)(drow + q * 4 + 2) = make_float2(v.z, v.w);
        }
    }

    float w[25];
#pragma unroll
    for (int i = 0; i < 25; i++) w[i] = __ldg(&cw[c * 25 + i]);
    float bias = __ldg(&cb[c]);
    __syncthreads();

    int xcol = tid & 63;
    int y0   = (tid >> 6) * 16;
    __half* dst = g_xs_h + (size_t)bc * LL;

    float win[5][5];
#pragma unroll
    for (int dy = 0; dy < 4; dy++)
#pragma unroll
        for (int dx = 0; dx < 5; dx++)
            win[dy][dx] = s[(y0 + dy) * 68 + xcol + dx];

#pragma unroll
    for (int i = 0; i < 16; i++) {
        int y = y0 + i;
#pragma unroll
        for (int dx = 0; dx < 5; dx++)
            win[4][dx] = s[(y + 4) * 68 + xcol + dx];

        float acc0 = bias, acc1 = 0.f;
#pragma unroll
        for (int dy = 0; dy < 5; dy++) {
#pragma unroll
            for (int dx = 0; dx < 5; dx++) {
                if (((dy * 5 + dx) & 1) == 0) acc0 = fmaf(win[dy][dx], w[dy*5+dx], acc0);
                else                          acc1 = fmaf(win[dy][dx], w[dy*5+dx], acc1);
            }
        }
        float acc = acc0 + acc1;

        float e = exp2f(-acc * 1.44269504f);
        dst[y * WW + xcol] = __float2half_rn(__fdividef(acc, 1.f + e));

#pragma unroll
        for (int dy = 0; dy < 4; dy++)
#pragma unroll
            for (int dx = 0; dx < 5; dx++)
                win[dy][dx] = win[dy + 1][dx];
    }
}

// ---------------------------------------------------------------------------
// K2: fused x_proj + dt-projection + softplus (R13 form, unchanged).
// ---------------------------------------------------------------------------
__global__ __launch_bounds__(256) void xproj_delta_kernel(
    const float* __restrict__ xw,     // (14, C)
    const float* __restrict__ dtw,    // (C, 12)
    const float* __restrict__ dtb)    // (C,)
{
    __shared__ float sw [96 * 32];    // [ci][half][16]
    __shared__ float sdt[96 * 32];    // [ci][half][16]
    __shared__ float sdb[CC];
    int t = threadIdx.x;
    for (int i = t; i < 96 * 32; i += 256) { sw[i] = 0.f; sdt[i] = 0.f; }
    __syncthreads();
    for (int i = t; i < NK * CC; i += 256) {
        int k = i / CC, c = i % CC;
        int ci = c % 96, hf = c / 96;
        sw[ci * 32 + hf * 16 + k] = xw[i];
    }
    for (int i = t; i < CC * RR; i += 256) {
        int c = i / RR, r = i % RR;
        int ci = c % 96, hf = c / 96;
        sdt[ci * 32 + hf * 16 + r] = dtw[i];
    }
    for (int i = t; i < CC; i += 256) sdb[i] = dtb[i];
    __syncthreads();

    int half = t & 1;
    int li   = t >> 1;
    int b = blockIdx.y;
    int l = blockIdx.x * 128 + li;
    const __half* xs = g_xs_h + (size_t)b * CC * LL + l;
    int cbase = half * 96;

    float acc[NK];
#pragma unroll
    for (int k = 0; k < NK; k++) acc[k] = 0.f;

#pragma unroll 8
    for (int ci = 0; ci < 96; ci++) {
        int c = cbase + ci;
        float v = __half2float(xs[(size_t)c * LL]);
        const float4* wp4 = (const float4*)&sw[ci * 32 + half * 16];
        float4 w0 = wp4[0], w1 = wp4[1], w2 = wp4[2], w3 = wp4[3];
        acc[0]  = fmaf(w0.x, v, acc[0]);
        acc[1]  = fmaf(w0.y, v, acc[1]);
        acc[2]  = fmaf(w0.z, v, acc[2]);
        acc[3]  = fmaf(w0.w, v, acc[3]);
        acc[4]  = fmaf(w1.x, v, acc[4]);
        acc[5]  = fmaf(w1.y, v, acc[5]);
        acc[6]  = fmaf(w1.z, v, acc[6]);
        acc[7]  = fmaf(w1.w, v, acc[7]);
        acc[8]  = fmaf(w2.x, v, acc[8]);
        acc[9]  = fmaf(w2.y, v, acc[9]);
        acc[10] = fmaf(w2.z, v, acc[10]);
        acc[11] = fmaf(w2.w, v, acc[11]);
        acc[12] = fmaf(w3.x, v, acc[12]);
        acc[13] = fmaf(w3.y, v, acc[13]);
    }

#pragma unroll
    for (int k = 0; k < NK; k++)
        acc[k] += __shfl_xor_sync(0xffffffffu, acc[k], 1);

    if (half == 0) {
        float* bcp = g_bc + (size_t)b * 2 * LL + l;
        bcp[0]  = acc[12];
        bcp[LL] = acc[13];
    }

    __half* dl = g_delta_h + (size_t)b * CC * LL + l;
#pragma unroll 4
    for (int ci = 0; ci < 96; ci++) {
        int c = cbase + ci;
        const float4* dwp = (const float4*)&sdt[ci * 32 + half * 16];
        float4 d0 = dwp[0], d1 = dwp[1], d2 = dwp[2];
        float dxv = sdb[c];
        dxv = fmaf(d0.x, acc[0], dxv);
        dxv = fmaf(d0.y, acc[1], dxv);
        dxv = fmaf(d0.z, acc[2], dxv);
        dxv = fmaf(d0.w, acc[3], dxv);
        dxv = fmaf(d1.x, acc[4], dxv);
        dxv = fmaf(d1.y, acc[5], dxv);
        dxv = fmaf(d1.z, acc[6], dxv);
        dxv = fmaf(d1.w, acc[7], dxv);
        dxv = fmaf(d2.x, acc[8], dxv);
        dxv = fmaf(d2.y, acc[9], dxv);
        dxv = fmaf(d2.z, acc[10], dxv);
        dxv = fmaf(d2.w, acc[11], dxv);

        float tx  = __log2f(1.f + exp2f(dxv * 1.44269504f)) * 0.69314718f;
        float spx = (dxv > 20.f) ? dxv : tx;
        dl[(size_t)c * LL] = __float2half_rn(spx);
    }
}

// ---------------------------------------------------------------------------
// K3: selective scan (d_state=1) + output. 512 threads per (b,c) row;
// warp owns 256 contiguous l's (2 chunks of 128); a / delta*B*x cached.
// ---------------------------------------------------------------------------
#define TPB3 512
#define NCH  2

__global__ __launch_bounds__(TPB3) void scan_kernel(
    const float* __restrict__ A_logs,
    const float* __restrict__ Ds,
    float* __restrict__ out)
{
    int bc = blockIdx.x;
    int b = bc / CC, c = bc % CC;
    int t = threadIdx.x;
    int lane = t & 31, wid = t >> 5;   // 16 warps
    int wbase = wid * 256;

    const __half* xs_row = g_xs_h    + (size_t)bc * LL;
    const __half* dl_row = g_delta_h + (size_t)bc * LL;
    const float*  Bs_row = g_bc + (size_t)b * 2 * LL;
    const float*  Cs_row = Bs_row + LL;

    float Dv  = __ldg(&Ds[c]);
    float Al2 = -1.44269504f * __expf(__ldg(&A_logs[c]));

    float av[NCH][4], btv[NCH][4], xv[NCH][4];
    float Ain[NCH], Bin[NCH];
    float carryA = 1.f, carryB = 0.f;

#pragma unroll
    for (int j = 0; j < NCH; j++) {
        int l = wbase + j * 128 + lane * 4;
        uint2 rawd = *(const uint2*)(dl_row + l);
        float2 d01 = __half22float2(*(__half2*)&rawd.x);
        float2 d23 = __half22float2(*(__half2*)&rawd.y);
        float dvk[4] = {d01.x, d01.y, d23.x, d23.y};
        uint2 rawx = *(const uint2*)(xs_row + l);
        float2 x01 = __half22float2(*(__half2*)&rawx.x);
        float2 x23 = __half22float2(*(__half2*)&rawx.y);
        xv[j][0]=x01.x; xv[j][1]=x01.y; xv[j][2]=x23.x; xv[j][3]=x23.y;
        float4 b4 = *(const float4*)(Bs_row + l);
        float bsv[4] = {b4.x, b4.y, b4.z, b4.w};

        float Ac = 1.f, Bc = 0.f;
#pragma unroll
        for (int k = 0; k < 4; k++) {
            float a  = exp2f(Al2 * dvk[k]);
            float bt = dvk[k] * bsv[k] * xv[j][k];
            av[j][k]  = a;
            btv[j][k] = bt;
            Ac = a * Ac;
            Bc = fmaf(a, Bc, bt);
        }

        float Asc = Ac, Bsc = Bc;
#pragma unroll
        for (int off = 1; off < 32; off <<= 1) {
            float aU = __shfl_up_sync(0xffffffffu, Asc, off);
            float bU = __shfl_up_sync(0xffffffffu, Bsc, off);
            if (lane >= off) { Bsc = fmaf(Asc, bU, Bsc); Asc *= aU; }
        }
        float aEx = __shfl_up_sync(0xffffffffu, Asc, 1);
        float bEx = __shfl_up_sync(0xffffffffu, Bsc, 1);
        if (lane == 0) { aEx = 1.f; bEx = 0.f; }
        Ain[j] = aEx * carryA;
        Bin[j] = fmaf(aEx, carryB, bEx);
        float aT = __shfl_sync(0xffffffffu, Asc, 31);
        float bT = __shfl_sync(0xffffffffu, Bsc, 31);
        carryB = fmaf(aT, carryB, bT);
        carryA = aT * carryA;
    }

    __shared__ float swA[TPB3/32], swB[TPB3/32];
    if (lane == 0) { swA[wid] = carryA; swB[wid] = carryB; }
    __syncthreads();
    float Hws = 0.f;
    for (int wp = 0; wp < wid; wp++) Hws = fmaf(swA[wp], Hws, swB[wp]);

    float* out_row = out + (size_t)bc * LL;
#pragma unroll
    for (int j = 0; j < NCH; j++) {
        int l = wbase + j * 128 + lane * 4;
        float4 c4 = *(const float4*)(Cs_row + l);
        float csv[4] = {c4.x, c4.y, c4.z, c4.w};
        float h = fmaf(Ain[j], Hws, Bin[j]);
        float yo[4];
#pragma unroll
        for (int k = 0; k < 4; k++) {
            h = fmaf(av[j][k], h, btv[j][k]);
            yo[k] = fmaf(h, csv[k], xv[j][k] * Dv);
        }
        *(float4*)(out_row + l) = make_float4(yo[0], yo[1], yo[2], yo[3]);
    }
}

// ---------------------------------------------------------------------------
extern "C" void kernel_launch(void* const* d_in, const int* in_sizes, int n_in,
                              void* d_out, int out_size)
{
    const float* x        = (const float*)d_in[0];
    const float* conv_w   = (const float*)d_in[1];
    const float* conv_b   = (const float*)d_in[2];
    const float* x_proj_w = (const float*)d_in[3];
    const float* dt_w     = (const float*)d_in[4];
    const float* dt_b     = (const float*)d_in[5];
    const float* A_logs   = (const float*)d_in[6];
    const float* Ds       = (const float*)d_in[7];
    float* out = (float*)d_out;

    conv_silu_kernel<<<BB * CC, 256>>>(x, conv_w, conv_b);
    xproj_delta_kernel<<<dim3(LL / 128, BB), 256>>>(x_proj_w, dt_w, dt_b);
    scan_kernel<<<BB * CC, TPB3>>>(A_logs, Ds, out);
}